// round 1
// baseline (speedup 1.0000x reference)
#include <cuda_runtime.h>
#include <math.h>

// Problem constants
constexpr int C_B    = 2;
constexpr int C_T    = 2048;
constexpr int C_HID  = 2048;
constexpr int C_H    = 16;
constexpr int C_D    = 128;
constexpr int C_QC   = 512;
constexpr int C_WIN  = 512;
constexpr int C_G    = 4;
constexpr int C_INTER= 2048;
constexpr int C_TOK  = C_B * C_T;        // 4096 tokens

// Scratch (device globals: no allocation allowed)
__device__ float g_hc [C_TOK * C_QC];          // h @ wq_comp            (4096 x 512)
__device__ float g_q  [C_TOK * C_H * C_D];     // q after up-proj / rope (4096 x 2048)
__device__ float g_k  [C_TOK * C_D];           // k                      (4096 x 128)
__device__ float g_v  [C_TOK * C_D];           // v                      (4096 x 128)
__device__ float g_att[C_TOK * C_H * C_D];     // attention output       (4096 x 2048)
__device__ float g_y1 [C_TOK * C_G * C_INTER]; // grouped out_w1 result  (4096 x 8192)

// ---------------------------------------------------------------------------
// Generic tiled SGEMM: C[M,N] = A[M,K] @ B[K,N], row-major, arbitrary ld.
// Requires: M % BM == 0, N % BN == 0, K % BK == 0, lda/ldb multiples of 4.
// ---------------------------------------------------------------------------
template<int BM, int BN, int BK, int TM, int TN>
__global__ void sgemm_kernel(const float* __restrict__ A,
                             const float* __restrict__ B,
                             float* __restrict__ C,
                             int K, int lda, int ldb, int ldc) {
    constexpr int TX = BN / TN;
    constexpr int TY = BM / TM;
    constexpr int THREADS = TX * TY;
    constexpr int A_F4 = BM * BK / 4;
    constexpr int B_F4 = BK * BN / 4;

    __shared__ float As[BK][BM];
    __shared__ float Bs[BK][BN];

    const int tid = threadIdx.x;
    const int tx  = tid % TX;
    const int ty  = tid / TX;

    const float* Ab = A + (size_t)blockIdx.y * BM * lda;
    const float* Bp = B + (size_t)blockIdx.x * BN;

    float acc[TM][TN];
#pragma unroll
    for (int i = 0; i < TM; i++)
#pragma unroll
        for (int j = 0; j < TN; j++) acc[i][j] = 0.f;

    for (int k0 = 0; k0 < K; k0 += BK) {
#pragma unroll
        for (int i = tid; i < A_F4; i += THREADS) {
            int r  = i / (BK / 4);
            int c4 = (i % (BK / 4)) * 4;
            float4 av = *(const float4*)(Ab + (size_t)r * lda + k0 + c4);
            As[c4 + 0][r] = av.x;
            As[c4 + 1][r] = av.y;
            As[c4 + 2][r] = av.z;
            As[c4 + 3][r] = av.w;
        }
#pragma unroll
        for (int i = tid; i < B_F4; i += THREADS) {
            int r  = i / (BN / 4);
            int c4 = (i % (BN / 4)) * 4;
            *(float4*)&Bs[r][c4] = *(const float4*)(Bp + (size_t)(k0 + r) * ldb + c4);
        }
        __syncthreads();

#pragma unroll
        for (int kk = 0; kk < BK; ++kk) {
            float ar[TM], br[TN];
#pragma unroll
            for (int i = 0; i < TM; i++) ar[i] = As[kk][ty * TM + i];
#pragma unroll
            for (int j = 0; j < TN; j++) br[j] = Bs[kk][tx * TN + j];
#pragma unroll
            for (int i = 0; i < TM; i++)
#pragma unroll
                for (int j = 0; j < TN; j++)
                    acc[i][j] += ar[i] * br[j];
        }
        __syncthreads();
    }

#pragma unroll
    for (int i = 0; i < TM; i++) {
        float* Cr = C + (size_t)(blockIdx.y * BM + ty * TM + i) * ldc
                      + blockIdx.x * BN + tx * TN;
#pragma unroll
        for (int j = 0; j < TN; j += 4) {
            float4 cv = make_float4(acc[i][j], acc[i][j+1], acc[i][j+2], acc[i][j+3]);
            *(float4*)(Cr + j) = cv;
        }
    }
}

// ---------------------------------------------------------------------------
// Partial RoPE (first 64 dims, pair (d, d+32)) + RMSNorm over D=128, in-place.
// One warp per row of 128 floats. pos = (row / heads) % T.
// ---------------------------------------------------------------------------
__global__ void rope_norm_kernel(float* __restrict__ x, const float* __restrict__ w,
                                 int nrows, int heads) {
    int gid  = blockIdx.x * blockDim.x + threadIdx.x;
    int wid  = gid >> 5;
    int lane = threadIdx.x & 31;
    if (wid >= nrows) return;
    int pos = (wid / heads) % C_T;

    float* row = x + (size_t)wid * C_D;
    float a  = row[lane];
    float b2 = row[lane + 32];
    float c  = row[lane + 64];
    float e  = row[lane + 96];

    // inv freq for rotation index = lane (0..31): theta^{-(2*lane)/64}
    double invd = exp(-log(10000.0) * (double)(2 * lane) / 64.0);
    double ang  = (double)pos * invd;
    float cs = (float)cos(ang);
    float sn = (float)sin(ang);

    float r1 = a * cs - b2 * sn;
    float r2 = a * sn + b2 * cs;

    float ss = r1 * r1 + r2 * r2 + c * c + e * e;
#pragma unroll
    for (int off = 16; off; off >>= 1) ss += __shfl_xor_sync(0xffffffffu, ss, off);
    float rms = rsqrtf(ss * (1.0f / 128.0f) + 1e-6f);

    row[lane]      = r1 * rms * w[lane];
    row[lane + 32] = r2 * rms * w[lane + 32];
    row[lane + 64] = c  * rms * w[lane + 64];
    row[lane + 96] = e  * rms * w[lane + 96];
}

// ---------------------------------------------------------------------------
// Sliding-window MQA attention with sink logit. One warp per (b, h, t).
// Online softmax over keys s in [max(0, t-WIN+1), t], then fold in sink.
// ---------------------------------------------------------------------------
__global__ void attn_kernel(const float* __restrict__ q,
                            const float* __restrict__ k,
                            const float* __restrict__ v,
                            const float* __restrict__ sink,
                            float* __restrict__ att) {
    int gid  = blockIdx.x * blockDim.x + threadIdx.x;
    int wid  = gid >> 5;
    int lane = threadIdx.x & 31;
    if (wid >= C_B * C_H * C_T) return;

    int t = wid % C_T;
    int h = (wid / C_T) % C_H;
    int b = wid / (C_T * C_H);
    int token = b * C_T + t;

    const float* qrow = q + (size_t)token * (C_H * C_D) + h * C_D;
    float q0 = qrow[lane], q1 = qrow[lane + 32], q2 = qrow[lane + 64], q3 = qrow[lane + 96];

    const float scale = 0.08838834764831845f;   // 1/sqrt(128)
    float m = -1e30f, ssum = 0.f;
    float a0 = 0.f, a1 = 0.f, a2 = 0.f, a3 = 0.f;

    int s0 = t - (C_WIN - 1);
    if (s0 < 0) s0 = 0;

    for (int s = s0; s <= t; ++s) {
        const float* krow = k + (size_t)(b * C_T + s) * C_D;
        float d = q0 * krow[lane] + q1 * krow[lane + 32]
                + q2 * krow[lane + 64] + q3 * krow[lane + 96];
#pragma unroll
        for (int off = 16; off; off >>= 1) d += __shfl_xor_sync(0xffffffffu, d, off);
        d *= scale;

        float mn   = fmaxf(m, d);
        float corr = __expf(m - mn);
        float p    = __expf(d - mn);

        const float* vrow = v + (size_t)(b * C_T + s) * C_D;
        ssum = ssum * corr + p;
        a0 = a0 * corr + p * vrow[lane];
        a1 = a1 * corr + p * vrow[lane + 32];
        a2 = a2 * corr + p * vrow[lane + 64];
        a3 = a3 * corr + p * vrow[lane + 96];
        m = mn;
    }

    // sink logit contributes to denominator only
    float sl   = sink[h];
    float mn   = fmaxf(m, sl);
    float corr = __expf(m - mn);
    ssum = ssum * corr + __expf(sl - mn);
    float inv = 1.0f / ssum;

    float* orow = att + (size_t)token * (C_H * C_D) + h * C_D;
    orow[lane]      = a0 * corr * inv;
    orow[lane + 32] = a1 * corr * inv;
    orow[lane + 64] = a2 * corr * inv;
    orow[lane + 96] = a3 * corr * inv;
}

// ---------------------------------------------------------------------------
// Launch
// ---------------------------------------------------------------------------
extern "C" void kernel_launch(void* const* d_in, const int* in_sizes, int n_in,
                              void* d_out, int out_size) {
    const float* h_in     = (const float*)d_in[0];
    const float* wq_comp  = (const float*)d_in[1];
    const float* wq_up    = (const float*)d_in[2];
    const float* wk       = (const float*)d_in[3];
    const float* wv       = (const float*)d_in[4];
    const float* q_norm_w = (const float*)d_in[5];
    const float* k_norm_w = (const float*)d_in[6];
    const float* sink     = (const float*)d_in[7];
    const float* out_w1   = (const float*)d_in[8];
    const float* out_w2   = (const float*)d_in[9];
    float* out = (float*)d_out;

    float *hc, *q, *k, *v, *att, *y1;
    cudaGetSymbolAddress((void**)&hc,  g_hc);
    cudaGetSymbolAddress((void**)&q,   g_q);
    cudaGetSymbolAddress((void**)&k,   g_k);
    cudaGetSymbolAddress((void**)&v,   g_v);
    cudaGetSymbolAddress((void**)&att, g_att);
    cudaGetSymbolAddress((void**)&y1,  g_y1);

    // 1) hc = h @ wq_comp   [4096,2048]x[2048,512]
    sgemm_kernel<128,128,8,8,8><<<dim3(C_QC/128, C_TOK/128), 256>>>(
        h_in, wq_comp, hc, C_HID, C_HID, C_QC, C_QC);

    // 2) q = hc @ wq_up     [4096,512]x[512,2048]
    sgemm_kernel<128,128,8,8,8><<<dim3(C_H*C_D/128, C_TOK/128), 256>>>(
        hc, wq_up, q, C_QC, C_QC, C_H*C_D, C_H*C_D);

    // 3) k = h @ wk         [4096,2048]x[2048,128]   (narrow N -> 64-row tiles)
    sgemm_kernel<64,128,8,8,8><<<dim3(1, C_TOK/64), 128>>>(
        h_in, wk, k, C_HID, C_HID, C_D, C_D);

    // 4) v = h @ wv
    sgemm_kernel<64,128,8,8,8><<<dim3(1, C_TOK/64), 128>>>(
        h_in, wv, v, C_HID, C_HID, C_D, C_D);

    // 5) RoPE + RMSNorm on q (65536 rows) and k (4096 rows)
    {
        int rows = C_TOK * C_H;
        int blocks = (rows * 32 + 255) / 256;
        rope_norm_kernel<<<blocks, 256>>>(q, q_norm_w, rows, C_H);
    }
    {
        int rows = C_TOK;
        int blocks = (rows * 32 + 255) / 256;
        rope_norm_kernel<<<blocks, 256>>>(k, k_norm_w, rows, 1);
    }

    // 6) attention -> att (stored [token][h][d] == (B,T,H,D), ready for grouping)
    {
        int warps = C_B * C_H * C_T;
        int blocks = (warps * 32 + 255) / 256;
        attn_kernel<<<blocks, 256>>>(q, k, v, sink, att);
    }

    // 7) grouped out_w1: per group g, [4096,512]x[512,2048] -> y1[:, g*2048:(g+1)*2048]
    for (int g = 0; g < C_G; ++g) {
        sgemm_kernel<128,128,8,8,8><<<dim3(C_INTER/128, C_TOK/128), 256>>>(
            att + g * ((C_H / C_G) * C_D),
            out_w1 + (size_t)g * (C_H / C_G) * C_D * C_INTER,
            y1 + g * C_INTER,
            (C_H / C_G) * C_D,      // K = 512
            C_H * C_D,              // lda = 2048
            C_INTER,                // ldb = 2048
            C_G * C_INTER);         // ldc = 8192
    }

    // 8) out = y1 @ out_w2  [4096,8192]x[8192,2048]
    sgemm_kernel<128,128,8,8,8><<<dim3(C_HID/128, C_TOK/128), 256>>>(
        y1, out_w2, out, C_G*C_INTER, C_G*C_INTER, C_HID, C_HID);
}

// round 2
// speedup vs baseline: 1.7831x; 1.7831x over previous
#include <cuda_runtime.h>
#include <math.h>
#include <stdint.h>

// Problem constants
constexpr int C_B    = 2;
constexpr int C_T    = 2048;
constexpr int C_HID  = 2048;
constexpr int C_H    = 16;
constexpr int C_D    = 128;
constexpr int C_QC   = 512;
constexpr int C_WIN  = 512;
constexpr int C_G    = 4;
constexpr int C_INTER= 2048;
constexpr int C_TOK  = C_B * C_T;        // 4096 tokens

// Scratch (device globals: no allocation allowed)
__device__ float g_hc [C_TOK * C_QC];          // h @ wq_comp            (4096 x 512)
__device__ float g_q  [C_TOK * C_H * C_D];     // q after up-proj / rope (4096 x 2048)
__device__ float g_kv [C_TOK * 2 * C_D];       // [token][k(128) | v(128)]
__device__ float g_wkv[C_HID * 2 * C_D];       // packed wk|wv           (2048 x 256)
__device__ float g_att[C_TOK * C_H * C_D];     // attention output       (4096 x 2048)
__device__ float g_y1 [C_TOK * C_G * C_INTER]; // grouped out_w1 result  (4096 x 8192)

__device__ __forceinline__ uint32_t f2tf32(float f) {
    uint32_t r;
    asm("cvt.rna.tf32.f32 %0, %1;" : "=r"(r) : "f"(f));
    return r;
}

__device__ __forceinline__ void mma_tf32(float& c0, float& c1, float& c2, float& c3,
                                         uint32_t a0, uint32_t a1, uint32_t a2, uint32_t a3,
                                         uint32_t b0, uint32_t b1) {
    asm volatile(
        "mma.sync.aligned.m16n8k8.row.col.f32.tf32.tf32.f32 "
        "{%0,%1,%2,%3}, {%4,%5,%6,%7}, {%8,%9}, {%0,%1,%2,%3};"
        : "+f"(c0), "+f"(c1), "+f"(c2), "+f"(c3)
        : "r"(a0), "r"(a1), "r"(a2), "r"(a3), "r"(b0), "r"(b1));
}

// ---------------------------------------------------------------------------
// TF32 tensor-core GEMM: C[M,N] = A[M,K] @ B[K,N], row-major, fp32 accumulate.
// Requires M % BM == 0, N % BN == 0, K % BK == 0, lda/ldb div by 4.
// ---------------------------------------------------------------------------
template<int BM, int BN, int BK, int WARPS_M, int WARPS_N>
__global__ void tf32_gemm(const float* __restrict__ A,
                          const float* __restrict__ B,
                          float* __restrict__ C,
                          int K, int lda, int ldb, int ldc) {
    constexpr int THREADS = WARPS_M * WARPS_N * 32;
    constexpr int WM = BM / WARPS_M;
    constexpr int WN = BN / WARPS_N;
    constexpr int MI = WM / 16;
    constexpr int NI = WN / 8;
    constexpr int A_F4 = BM * BK / 4;
    constexpr int B_F4 = BK * BN / 4;

    __shared__ uint32_t As[BK][BM + 4];
    __shared__ uint32_t Bs[BK][BN + 4];

    const int tid  = threadIdx.x;
    const int warp = tid >> 5;
    const int lane = tid & 31;
    const int grp  = lane >> 2;   // 0..7
    const int tig  = lane & 3;    // 0..3
    const int wm   = (warp / WARPS_N) * WM;
    const int wn   = (warp % WARPS_N) * WN;

    const float* Ab = A + (size_t)blockIdx.y * BM * lda;
    const float* Bp = B + (size_t)blockIdx.x * BN;

    float acc[MI][NI][4];
#pragma unroll
    for (int i = 0; i < MI; i++)
#pragma unroll
        for (int j = 0; j < NI; j++)
#pragma unroll
            for (int r = 0; r < 4; r++) acc[i][j][r] = 0.f;

    for (int k0 = 0; k0 < K; k0 += BK) {
#pragma unroll
        for (int i = tid; i < A_F4; i += THREADS) {
            int r  = i / (BK / 4);
            int c4 = (i % (BK / 4)) * 4;
            float4 av = *(const float4*)(Ab + (size_t)r * lda + k0 + c4);
            As[c4 + 0][r] = f2tf32(av.x);
            As[c4 + 1][r] = f2tf32(av.y);
            As[c4 + 2][r] = f2tf32(av.z);
            As[c4 + 3][r] = f2tf32(av.w);
        }
#pragma unroll
        for (int i = tid; i < B_F4; i += THREADS) {
            int r  = i / (BN / 4);
            int c4 = (i % (BN / 4)) * 4;
            float4 bv = *(const float4*)(Bp + (size_t)(k0 + r) * ldb + c4);
            Bs[r][c4 + 0] = f2tf32(bv.x);
            Bs[r][c4 + 1] = f2tf32(bv.y);
            Bs[r][c4 + 2] = f2tf32(bv.z);
            Bs[r][c4 + 3] = f2tf32(bv.w);
        }
        __syncthreads();

#pragma unroll
        for (int kk = 0; kk < BK; kk += 8) {
            uint32_t af[MI][4];
            uint32_t bf[NI][2];
#pragma unroll
            for (int mi = 0; mi < MI; mi++) {
                int m = wm + mi * 16;
                af[mi][0] = As[kk + tig    ][m + grp    ];
                af[mi][1] = As[kk + tig    ][m + grp + 8];
                af[mi][2] = As[kk + tig + 4][m + grp    ];
                af[mi][3] = As[kk + tig + 4][m + grp + 8];
            }
#pragma unroll
            for (int ni = 0; ni < NI; ni++) {
                int n = wn + ni * 8;
                bf[ni][0] = Bs[kk + tig    ][n + grp];
                bf[ni][1] = Bs[kk + tig + 4][n + grp];
            }
#pragma unroll
            for (int mi = 0; mi < MI; mi++)
#pragma unroll
                for (int ni = 0; ni < NI; ni++)
                    mma_tf32(acc[mi][ni][0], acc[mi][ni][1], acc[mi][ni][2], acc[mi][ni][3],
                             af[mi][0], af[mi][1], af[mi][2], af[mi][3],
                             bf[ni][0], bf[ni][1]);
        }
        __syncthreads();
    }

    // Epilogue: c0,c1 at (grp, tig*2 / +1), c2,c3 at (grp+8, ...)
#pragma unroll
    for (int mi = 0; mi < MI; mi++) {
        int m0 = blockIdx.y * BM + wm + mi * 16 + grp;
#pragma unroll
        for (int ni = 0; ni < NI; ni++) {
            int n = blockIdx.x * BN + wn + ni * 8 + tig * 2;
            *(float2*)(C + (size_t)m0 * ldc + n)       = make_float2(acc[mi][ni][0], acc[mi][ni][1]);
            *(float2*)(C + (size_t)(m0 + 8) * ldc + n) = make_float2(acc[mi][ni][2], acc[mi][ni][3]);
        }
    }
}

// ---------------------------------------------------------------------------
// Pack wk|wv into a single [HID, 256] weight so K/V is one wide GEMM.
// ---------------------------------------------------------------------------
__global__ void pack_wkv_kernel(const float* __restrict__ wk,
                                const float* __restrict__ wv,
                                float* __restrict__ wkv) {
    int idx = blockIdx.x * blockDim.x + threadIdx.x;   // over HID*128
    if (idx >= C_HID * C_D) return;
    int k = idx / C_D, c = idx % C_D;
    wkv[(size_t)k * (2 * C_D) + c]       = wk[idx];
    wkv[(size_t)k * (2 * C_D) + C_D + c] = wv[idx];
}

// ---------------------------------------------------------------------------
// Partial RoPE (pairs (d, d+32), d<32) + RMSNorm over D=128, in-place.
// One warp per row. pos = (row / heads) % T. row stride parametrized.
// ---------------------------------------------------------------------------
__global__ void rope_norm_kernel(float* __restrict__ x, const float* __restrict__ w,
                                 int nrows, int heads, int stride) {
    int gid  = blockIdx.x * blockDim.x + threadIdx.x;
    int wid  = gid >> 5;
    int lane = threadIdx.x & 31;
    if (wid >= nrows) return;
    int pos = (wid / heads) % C_T;

    float* row = x + (size_t)wid * stride;
    float a  = row[lane];
    float b2 = row[lane + 32];
    float c  = row[lane + 64];
    float e  = row[lane + 96];

    double invd = exp(-log(10000.0) * (double)(2 * lane) / 64.0);
    double ang  = (double)pos * invd;
    float cs = (float)cos(ang);
    float sn = (float)sin(ang);

    float r1 = a * cs - b2 * sn;
    float r2 = a * sn + b2 * cs;

    float ss = r1 * r1 + r2 * r2 + c * c + e * e;
#pragma unroll
    for (int off = 16; off; off >>= 1) ss += __shfl_xor_sync(0xffffffffu, ss, off);
    float rms = rsqrtf(ss * (1.0f / 128.0f) + 1e-6f);

    row[lane]      = r1 * rms * w[lane];
    row[lane + 32] = r2 * rms * w[lane + 32];
    row[lane + 64] = c  * rms * w[lane + 64];
    row[lane + 96] = e  * rms * w[lane + 96];
}

// ---------------------------------------------------------------------------
// Sliding-window MQA attention with sink logit. One warp per (b, h, t).
// ---------------------------------------------------------------------------
__global__ void attn_kernel(const float* __restrict__ q,
                            const float* __restrict__ kv,
                            const float* __restrict__ sink,
                            float* __restrict__ att) {
    int gid  = blockIdx.x * blockDim.x + threadIdx.x;
    int wid  = gid >> 5;
    int lane = threadIdx.x & 31;
    if (wid >= C_B * C_H * C_T) return;

    int t = wid % C_T;
    int h = (wid / C_T) % C_H;
    int b = wid / (C_T * C_H);
    int token = b * C_T + t;

    const float* qrow = q + (size_t)token * (C_H * C_D) + h * C_D;
    float q0 = qrow[lane], q1 = qrow[lane + 32], q2 = qrow[lane + 64], q3 = qrow[lane + 96];

    const float scale = 0.08838834764831845f;   // 1/sqrt(128)
    float m = -1e30f, ssum = 0.f;
    float a0 = 0.f, a1 = 0.f, a2 = 0.f, a3 = 0.f;

    int s0 = t - (C_WIN - 1);
    if (s0 < 0) s0 = 0;

    for (int s = s0; s <= t; ++s) {
        const float* krow = kv + (size_t)(b * C_T + s) * (2 * C_D);
        float d = q0 * krow[lane] + q1 * krow[lane + 32]
                + q2 * krow[lane + 64] + q3 * krow[lane + 96];
#pragma unroll
        for (int off = 16; off; off >>= 1) d += __shfl_xor_sync(0xffffffffu, d, off);
        d *= scale;

        float mn   = fmaxf(m, d);
        float corr = __expf(m - mn);
        float p    = __expf(d - mn);

        const float* vrow = krow + C_D;
        ssum = ssum * corr + p;
        a0 = a0 * corr + p * vrow[lane];
        a1 = a1 * corr + p * vrow[lane + 32];
        a2 = a2 * corr + p * vrow[lane + 64];
        a3 = a3 * corr + p * vrow[lane + 96];
        m = mn;
    }

    float sl   = sink[h];
    float mn   = fmaxf(m, sl);
    float corr = __expf(m - mn);
    ssum = ssum * corr + __expf(sl - mn);
    float inv = 1.0f / ssum;

    float* orow = att + (size_t)token * (C_H * C_D) + h * C_D;
    orow[lane]      = a0 * corr * inv;
    orow[lane + 32] = a1 * corr * inv;
    orow[lane + 64] = a2 * corr * inv;
    orow[lane + 96] = a3 * corr * inv;
}

// ---------------------------------------------------------------------------
// Launch
// ---------------------------------------------------------------------------
extern "C" void kernel_launch(void* const* d_in, const int* in_sizes, int n_in,
                              void* d_out, int out_size) {
    const float* h_in     = (const float*)d_in[0];
    const float* wq_comp  = (const float*)d_in[1];
    const float* wq_up    = (const float*)d_in[2];
    const float* wk       = (const float*)d_in[3];
    const float* wv       = (const float*)d_in[4];
    const float* q_norm_w = (const float*)d_in[5];
    const float* k_norm_w = (const float*)d_in[6];
    const float* sink     = (const float*)d_in[7];
    const float* out_w1   = (const float*)d_in[8];
    const float* out_w2   = (const float*)d_in[9];
    float* out = (float*)d_out;

    float *hc, *q, *kv, *wkv, *att, *y1;
    cudaGetSymbolAddress((void**)&hc,  g_hc);
    cudaGetSymbolAddress((void**)&q,   g_q);
    cudaGetSymbolAddress((void**)&kv,  g_kv);
    cudaGetSymbolAddress((void**)&wkv, g_wkv);
    cudaGetSymbolAddress((void**)&att, g_att);
    cudaGetSymbolAddress((void**)&y1,  g_y1);

    // 0) pack wk|wv -> wkv [2048,256]
    pack_wkv_kernel<<<(C_HID * C_D + 255) / 256, 256>>>(wk, wv, wkv);

    // 1) hc = h @ wq_comp   [4096,2048]x[2048,512]
    tf32_gemm<128,128,16,4,2><<<dim3(C_QC/128, C_TOK/128), 256>>>(
        h_in, wq_comp, hc, C_HID, C_HID, C_QC, C_QC);

    // 2) q = hc @ wq_up     [4096,512]x[512,2048]
    tf32_gemm<128,128,16,4,2><<<dim3(C_H*C_D/128, C_TOK/128), 256>>>(
        hc, wq_up, q, C_QC, C_QC, C_H*C_D, C_H*C_D);

    // 3) kv = h @ wkv       [4096,2048]x[2048,256]   (256 blocks for occupancy)
    tf32_gemm<64,64,32,2,2><<<dim3((2*C_D)/64, C_TOK/64), 128>>>(
        h_in, wkv, kv, C_HID, C_HID, 2*C_D, 2*C_D);

    // 4) RoPE + RMSNorm on q (65536 rows, stride 128) and k (4096 rows, stride 256)
    {
        int rows = C_TOK * C_H;
        rope_norm_kernel<<<(rows * 32 + 255) / 256, 256>>>(q, q_norm_w, rows, C_H, C_D);
    }
    {
        int rows = C_TOK;
        rope_norm_kernel<<<(rows * 32 + 255) / 256, 256>>>(kv, k_norm_w, rows, 1, 2*C_D);
    }

    // 5) attention -> att (stored [token][h][d])
    {
        int warps = C_B * C_H * C_T;
        attn_kernel<<<(warps * 32 + 255) / 256, 256>>>(q, kv, sink, att);
    }

    // 6) grouped out_w1: per group g, [4096,512]x[512,2048]
    for (int g = 0; g < C_G; ++g) {
        tf32_gemm<128,128,16,4,2><<<dim3(C_INTER/128, C_TOK/128), 256>>>(
            att + g * ((C_H / C_G) * C_D),
            out_w1 + (size_t)g * (C_H / C_G) * C_D * C_INTER,
            y1 + g * C_INTER,
            (C_H / C_G) * C_D,      // K = 512
            C_H * C_D,              // lda = 2048
            C_INTER,                // ldb = 2048
            C_G * C_INTER);         // ldc = 8192
    }

    // 7) out = y1 @ out_w2  [4096,8192]x[8192,2048]
    tf32_gemm<128,128,16,4,2><<<dim3(C_HID/128, C_TOK/128), 256>>>(
        y1, out_w2, out, C_G*C_INTER, C_G*C_INTER, C_HID, C_HID);
}

// round 3
// speedup vs baseline: 2.2435x; 1.2582x over previous
#include <cuda_runtime.h>
#include <math.h>
#include <stdint.h>

// Problem constants
constexpr int C_B    = 2;
constexpr int C_T    = 2048;
constexpr int C_HID  = 2048;
constexpr int C_H    = 16;
constexpr int C_D    = 128;
constexpr int C_QC   = 512;
constexpr int C_WIN  = 512;
constexpr int C_G    = 4;
constexpr int C_INTER= 2048;
constexpr int C_TOK  = C_B * C_T;

// Scratch
__device__ float g_hc [C_TOK * C_QC];
__device__ float g_q  [C_TOK * C_H * C_D];
__device__ float g_kv [C_TOK * 2 * C_D];
__device__ float g_wkv[C_HID * 2 * C_D];
__device__ float g_att[C_TOK * C_H * C_D];
__device__ float g_y1 [C_TOK * C_G * C_INTER];

__device__ __forceinline__ uint32_t f2tf32(float f) {
    uint32_t r;
    asm("cvt.rna.tf32.f32 %0, %1;" : "=r"(r) : "f"(f));
    return r;
}

__device__ __forceinline__ void mma_tf32(float& c0, float& c1, float& c2, float& c3,
                                         uint32_t a0, uint32_t a1, uint32_t a2, uint32_t a3,
                                         uint32_t b0, uint32_t b1) {
    asm volatile(
        "mma.sync.aligned.m16n8k8.row.col.f32.tf32.tf32.f32 "
        "{%0,%1,%2,%3}, {%4,%5,%6,%7}, {%8,%9}, {%0,%1,%2,%3};"
        : "+f"(c0), "+f"(c1), "+f"(c2), "+f"(c3)
        : "r"(a0), "r"(a1), "r"(a2), "r"(a3), "r"(b0), "r"(b1));
}

__device__ __forceinline__ void ldsm4(uint32_t& r0, uint32_t& r1, uint32_t& r2, uint32_t& r3,
                                      uint32_t addr) {
    asm volatile("ldmatrix.sync.aligned.m8n8.x4.shared.b16 {%0,%1,%2,%3}, [%4];"
                 : "=r"(r0), "=r"(r1), "=r"(r2), "=r"(r3) : "r"(addr));
}

// ---------------------------------------------------------------------------
// Pipelined tf32 tensor-core GEMM. 128x128 tile, BK=16, 8 warps (2x4).
// SPLIT=1: hi/lo tf32 decomposition (3 MMAs) for near-fp32 accuracy.
// Smem: A stored m-major [BM][20], B stored n-major [BN][20]; ldmatrix frags.
// ---------------------------------------------------------------------------
template<int SPLIT>
__global__ void __launch_bounds__(256, SPLIT ? 1 : 2)
mma_gemm(const float* __restrict__ A, const float* __restrict__ B,
         float* __restrict__ C, int K, int lda, int ldb, int ldc) {
    constexpr int BM = 128, BN = 128, BK = 16;
    constexpr int LDS_ = 20;                       // row stride (floats), 80B
    constexpr int PLANE = BM * LDS_;               // 2560 floats
    constexpr int STAGE = (SPLIT ? 4 : 2) * PLANE; // floats per stage

    extern __shared__ float sm[];

    const int tid  = threadIdx.x;
    const int warp = tid >> 5;
    const int lane = tid & 31;
    const int wm   = (warp >> 2) * 64;   // WARPS_M=2 -> WM=64, MI=4
    const int wn   = (warp & 3) * 32;    // WARPS_N=4 -> WN=32, NI=4
    const int grp  = lane >> 2;
    const int tig  = lane & 3;

    // ldmatrix lane addressing
    const int arow   = lane & 15;
    const int aoff16 = (lane >> 4) * 16;           // bytes
    const int bsel   = (lane >> 4) & 1;            // which n-subtile within pair
    const int boff16 = ((lane >> 3) & 1) * 16;     // k-half
    const int brow   = lane & 7;

    const uint32_t sbase = (uint32_t)__cvta_generic_to_shared(sm);

    const float* Ab = A + (size_t)blockIdx.y * BM * lda;
    const float* Bb = B + blockIdx.x * BN;

    float4 ar[2];
    float  br[2][4];

    float acc[4][4][4];
#pragma unroll
    for (int i = 0; i < 4; i++)
#pragma unroll
        for (int j = 0; j < 4; j++)
#pragma unroll
            for (int r = 0; r < 4; r++) acc[i][j][r] = 0.f;

    auto gload = [&](int k0) {
#pragma unroll
        for (int i = 0; i < 2; i++) {
            int t = tid + i * 256;
            int m = t >> 2, c4 = (t & 3) * 4;
            ar[i] = *(const float4*)(Ab + (size_t)m * lda + k0 + c4);
        }
#pragma unroll
        for (int i = 0; i < 2; i++) {
            int t = tid + i * 256;
            int n = t & 127, r4 = (t >> 7) * 4;
#pragma unroll
            for (int j = 0; j < 4; j++)
                br[i][j] = Bb[(size_t)(k0 + r4 + j) * ldb + n];
        }
    };

    auto sstore = [&](int st) {
        float* As_hi = sm + st * STAGE;
        float* Bs_hi = As_hi + PLANE;
        float* As_lo = Bs_hi + PLANE;
        float* Bs_lo = As_lo + PLANE;
#pragma unroll
        for (int i = 0; i < 2; i++) {
            int t = tid + i * 256;
            int m = t >> 2, c4 = (t & 3) * 4;
            float v[4] = {ar[i].x, ar[i].y, ar[i].z, ar[i].w};
            uint32_t h[4], l[4];
#pragma unroll
            for (int j = 0; j < 4; j++) {
                h[j] = f2tf32(v[j]);
                if (SPLIT) l[j] = f2tf32(v[j] - __uint_as_float(h[j]));
            }
            *(uint4*)(As_hi + m * LDS_ + c4) = make_uint4(h[0], h[1], h[2], h[3]);
            if (SPLIT)
                *(uint4*)(As_lo + m * LDS_ + c4) = make_uint4(l[0], l[1], l[2], l[3]);
        }
#pragma unroll
        for (int i = 0; i < 2; i++) {
            int t = tid + i * 256;
            int n = t & 127, r4 = (t >> 7) * 4;
            uint32_t h[4], l[4];
#pragma unroll
            for (int j = 0; j < 4; j++) {
                h[j] = f2tf32(br[i][j]);
                if (SPLIT) l[j] = f2tf32(br[i][j] - __uint_as_float(h[j]));
            }
            *(uint4*)(Bs_hi + n * LDS_ + r4) = make_uint4(h[0], h[1], h[2], h[3]);
            if (SPLIT)
                *(uint4*)(Bs_lo + n * LDS_ + r4) = make_uint4(l[0], l[1], l[2], l[3]);
        }
    };

    auto compute = [&](int st) {
        uint32_t stb   = sbase + st * STAGE * 4;
        uint32_t a_hi0 = stb + (uint32_t)(wm + arow) * (LDS_ * 4) + aoff16;
        uint32_t b_hi0 = stb + PLANE * 4
                       + (uint32_t)(wn + bsel * 8 + brow) * (LDS_ * 4) + boff16;
#pragma unroll
        for (int ks = 0; ks < 2; ks++) {
            const uint32_t kb = ks * 32;   // 8 floats * 4B
            uint32_t ah[4][4], bh[2][4];
#pragma unroll
            for (int mi = 0; mi < 4; mi++)
                ldsm4(ah[mi][0], ah[mi][1], ah[mi][2], ah[mi][3],
                      a_hi0 + mi * (16 * LDS_ * 4) + kb);
#pragma unroll
            for (int p = 0; p < 2; p++)
                ldsm4(bh[p][0], bh[p][1], bh[p][2], bh[p][3],
                      b_hi0 + p * (16 * LDS_ * 4) + kb);

            uint32_t al[4][4], bl[2][4];
            if (SPLIT) {
#pragma unroll
                for (int mi = 0; mi < 4; mi++)
                    ldsm4(al[mi][0], al[mi][1], al[mi][2], al[mi][3],
                          a_hi0 + 2 * PLANE * 4 + mi * (16 * LDS_ * 4) + kb);
#pragma unroll
                for (int p = 0; p < 2; p++)
                    ldsm4(bl[p][0], bl[p][1], bl[p][2], bl[p][3],
                          b_hi0 + 2 * PLANE * 4 + p * (16 * LDS_ * 4) + kb);
            }
#pragma unroll
            for (int mi = 0; mi < 4; mi++)
#pragma unroll
                for (int ni = 0; ni < 4; ni++) {
                    const int p = ni >> 1, q = (ni & 1) * 2;
                    mma_tf32(acc[mi][ni][0], acc[mi][ni][1], acc[mi][ni][2], acc[mi][ni][3],
                             ah[mi][0], ah[mi][1], ah[mi][2], ah[mi][3],
                             bh[p][q], bh[p][q + 1]);
                    if (SPLIT) {
                        mma_tf32(acc[mi][ni][0], acc[mi][ni][1], acc[mi][ni][2], acc[mi][ni][3],
                                 al[mi][0], al[mi][1], al[mi][2], al[mi][3],
                                 bh[p][q], bh[p][q + 1]);
                        mma_tf32(acc[mi][ni][0], acc[mi][ni][1], acc[mi][ni][2], acc[mi][ni][3],
                                 ah[mi][0], ah[mi][1], ah[mi][2], ah[mi][3],
                                 bl[p][q], bl[p][q + 1]);
                    }
                }
        }
    };

    const int KT = K / BK;
    gload(0);
    sstore(0);
    __syncthreads();
    int st = 0;
    for (int kt = 0; kt < KT; kt++) {
        if (kt + 1 < KT) gload((kt + 1) * BK);
        compute(st);
        if (kt + 1 < KT) {
            sstore(st ^ 1);
            __syncthreads();
            st ^= 1;
        }
    }

#pragma unroll
    for (int mi = 0; mi < 4; mi++) {
        int m0 = blockIdx.y * BM + wm + mi * 16 + grp;
#pragma unroll
        for (int ni = 0; ni < 4; ni++) {
            int n = blockIdx.x * BN + wn + ni * 8 + tig * 2;
            *(float2*)(C + (size_t)m0 * ldc + n)       = make_float2(acc[mi][ni][0], acc[mi][ni][1]);
            *(float2*)(C + (size_t)(m0 + 8) * ldc + n) = make_float2(acc[mi][ni][2], acc[mi][ni][3]);
        }
    }
}

// ---------------------------------------------------------------------------
__global__ void pack_wkv_kernel(const float* __restrict__ wk,
                                const float* __restrict__ wv,
                                float* __restrict__ wkv) {
    int idx = blockIdx.x * blockDim.x + threadIdx.x;
    if (idx >= C_HID * C_D) return;
    int k = idx / C_D, c = idx % C_D;
    wkv[(size_t)k * (2 * C_D) + c]       = wk[idx];
    wkv[(size_t)k * (2 * C_D) + C_D + c] = wv[idx];
}

// ---------------------------------------------------------------------------
__global__ void rope_norm_kernel(float* __restrict__ x, const float* __restrict__ w,
                                 int nrows, int heads, int stride) {
    int gid  = blockIdx.x * blockDim.x + threadIdx.x;
    int wid  = gid >> 5;
    int lane = threadIdx.x & 31;
    if (wid >= nrows) return;
    int pos = (wid / heads) % C_T;

    float* row = x + (size_t)wid * stride;
    float a  = row[lane];
    float b2 = row[lane + 32];
    float c  = row[lane + 64];
    float e  = row[lane + 96];

    double invd = exp(-log(10000.0) * (double)(2 * lane) / 64.0);
    double ang  = (double)pos * invd;
    float cs = (float)cos(ang);
    float sn = (float)sin(ang);

    float r1 = a * cs - b2 * sn;
    float r2 = a * sn + b2 * cs;

    float ss = r1 * r1 + r2 * r2 + c * c + e * e;
#pragma unroll
    for (int off = 16; off; off >>= 1) ss += __shfl_xor_sync(0xffffffffu, ss, off);
    float rms = rsqrtf(ss * (1.0f / 128.0f) + 1e-6f);

    row[lane]      = r1 * rms * w[lane];
    row[lane + 32] = r2 * rms * w[lane + 32];
    row[lane + 64] = c  * rms * w[lane + 64];
    row[lane + 96] = e  * rms * w[lane + 96];
}

// ---------------------------------------------------------------------------
// Attention: one block per (t, b); 16 warps = 16 heads sharing K/V via L1.
// ---------------------------------------------------------------------------
__global__ void __launch_bounds__(512)
attn_kernel(const float* __restrict__ q, const float* __restrict__ kv,
            const float* __restrict__ sink, float* __restrict__ att) {
    int t = blockIdx.x, b = blockIdx.y;
    int h    = threadIdx.x >> 5;
    int lane = threadIdx.x & 31;
    int token = b * C_T + t;

    const float* qrow = q + (size_t)token * (C_H * C_D) + h * C_D;
    float q0 = qrow[lane], q1 = qrow[lane + 32], q2 = qrow[lane + 64], q3 = qrow[lane + 96];

    const float scale = 0.08838834764831845f;
    float m = -1e30f, ssum = 0.f;
    float a0 = 0.f, a1 = 0.f, a2 = 0.f, a3 = 0.f;

    int s0 = t - (C_WIN - 1);
    if (s0 < 0) s0 = 0;

    for (int s = s0; s <= t; ++s) {
        const float* krow = kv + (size_t)(b * C_T + s) * (2 * C_D);
        float d = q0 * krow[lane] + q1 * krow[lane + 32]
                + q2 * krow[lane + 64] + q3 * krow[lane + 96];
#pragma unroll
        for (int off = 16; off; off >>= 1) d += __shfl_xor_sync(0xffffffffu, d, off);
        d *= scale;

        float mn   = fmaxf(m, d);
        float corr = __expf(m - mn);
        float p    = __expf(d - mn);

        const float* vrow = krow + C_D;
        ssum = ssum * corr + p;
        a0 = a0 * corr + p * vrow[lane];
        a1 = a1 * corr + p * vrow[lane + 32];
        a2 = a2 * corr + p * vrow[lane + 64];
        a3 = a3 * corr + p * vrow[lane + 96];
        m = mn;
    }

    float sl   = sink[h];
    float mn   = fmaxf(m, sl);
    float corr = __expf(m - mn);
    ssum = ssum * corr + __expf(sl - mn);
    float inv = 1.0f / ssum;

    float* orow = att + (size_t)token * (C_H * C_D) + h * C_D;
    orow[lane]      = a0 * corr * inv;
    orow[lane + 32] = a1 * corr * inv;
    orow[lane + 64] = a2 * corr * inv;
    orow[lane + 96] = a3 * corr * inv;
}

// ---------------------------------------------------------------------------
extern "C" void kernel_launch(void* const* d_in, const int* in_sizes, int n_in,
                              void* d_out, int out_size) {
    const float* h_in     = (const float*)d_in[0];
    const float* wq_comp  = (const float*)d_in[1];
    const float* wq_up    = (const float*)d_in[2];
    const float* wk       = (const float*)d_in[3];
    const float* wv       = (const float*)d_in[4];
    const float* q_norm_w = (const float*)d_in[5];
    const float* k_norm_w = (const float*)d_in[6];
    const float* sink     = (const float*)d_in[7];
    const float* out_w1   = (const float*)d_in[8];
    const float* out_w2   = (const float*)d_in[9];
    float* out = (float*)d_out;

    float *hc, *q, *kv, *wkv, *att, *y1;
    cudaGetSymbolAddress((void**)&hc,  g_hc);
    cudaGetSymbolAddress((void**)&q,   g_q);
    cudaGetSymbolAddress((void**)&kv,  g_kv);
    cudaGetSymbolAddress((void**)&wkv, g_wkv);
    cudaGetSymbolAddress((void**)&att, g_att);
    cudaGetSymbolAddress((void**)&y1,  g_y1);

    constexpr int SMEM_SPLIT  = 4 * 2560 * 2 * 4;  // 81920 B
    constexpr int SMEM_SINGLE = 2 * 2560 * 2 * 4;  // 40960 B
    cudaFuncSetAttribute(mma_gemm<1>, cudaFuncAttributeMaxDynamicSharedMemorySize, SMEM_SPLIT);
    cudaFuncSetAttribute(mma_gemm<0>, cudaFuncAttributeMaxDynamicSharedMemorySize, SMEM_SINGLE);

    // 0) pack wk|wv
    pack_wkv_kernel<<<(C_HID * C_D + 255) / 256, 256>>>(wk, wv, wkv);

    // 1) hc = h @ wq_comp  (split for precision)
    mma_gemm<1><<<dim3(C_QC / 128, C_TOK / 128), 256, SMEM_SPLIT>>>(
        h_in, wq_comp, hc, C_HID, C_HID, C_QC, C_QC);

    // 2) q = hc @ wq_up    (split)
    mma_gemm<1><<<dim3(C_H * C_D / 128, C_TOK / 128), 256, SMEM_SPLIT>>>(
        hc, wq_up, q, C_QC, C_QC, C_H * C_D, C_H * C_D);

    // 3) kv = h @ wkv      (split)
    mma_gemm<1><<<dim3(2 * C_D / 128, C_TOK / 128), 256, SMEM_SPLIT>>>(
        h_in, wkv, kv, C_HID, C_HID, 2 * C_D, 2 * C_D);

    // 4) RoPE + RMSNorm
    {
        int rows = C_TOK * C_H;
        rope_norm_kernel<<<(rows * 32 + 255) / 256, 256>>>(q, q_norm_w, rows, C_H, C_D);
    }
    {
        int rows = C_TOK;
        rope_norm_kernel<<<(rows * 32 + 255) / 256, 256>>>(kv, k_norm_w, rows, 1, 2 * C_D);
    }

    // 5) attention
    attn_kernel<<<dim3(C_T, C_B), 512>>>(q, kv, sink, att);

    // 6) grouped out_w1 (single-term tf32)
    for (int g = 0; g < C_G; ++g) {
        mma_gemm<0><<<dim3(C_INTER / 128, C_TOK / 128), 256, SMEM_SINGLE>>>(
            att + g * ((C_H / C_G) * C_D),
            out_w1 + (size_t)g * (C_H / C_G) * C_D * C_INTER,
            y1 + g * C_INTER,
            (C_H / C_G) * C_D, C_H * C_D, C_INTER, C_G * C_INTER);
    }

    // 7) out = y1 @ out_w2 (single-term tf32)
    mma_gemm<0><<<dim3(C_HID / 128, C_TOK / 128), 256, SMEM_SINGLE>>>(
        y1, out_w2, out, C_G * C_INTER, C_G * C_INTER, C_HID, C_HID);
}

// round 4
// speedup vs baseline: 2.4359x; 1.0858x over previous
#include <cuda_runtime.h>
#include <math.h>
#include <stdint.h>

// Problem constants
constexpr int C_B    = 2;
constexpr int C_T    = 2048;
constexpr int C_HID  = 2048;
constexpr int C_H    = 16;
constexpr int C_D    = 128;
constexpr int C_QC   = 512;
constexpr int C_WIN  = 512;
constexpr int C_G    = 4;
constexpr int C_INTER= 2048;
constexpr int C_TOK  = C_B * C_T;

// ---------------------------------------------------------------------------
// Scratch (device globals)
// ---------------------------------------------------------------------------
__device__ float g_h_hi [C_TOK * C_HID];
__device__ float g_h_lo [C_TOK * C_HID];
__device__ float g_hc_hi[C_TOK * C_QC];
__device__ float g_hc_lo[C_TOK * C_QC];
__device__ float g_q    [C_TOK * C_H * C_D];
__device__ float g_kv   [C_TOK * 2 * C_D];
__device__ float g_att  [C_TOK * C_H * C_D];
__device__ float g_y1   [C_TOK * C_G * C_INTER];
// Transposed (+rounded) weights: [N][K]
__device__ float g_wqcT_hi[C_QC * C_HID];
__device__ float g_wqcT_lo[C_QC * C_HID];
__device__ float g_wquT_hi[C_H * C_D * C_QC];
__device__ float g_wquT_lo[C_H * C_D * C_QC];
__device__ float g_wkvT_hi[2 * C_D * C_HID];
__device__ float g_wkvT_lo[2 * C_D * C_HID];
__device__ float g_w1T [C_G * C_INTER * (C_H / C_G) * C_D];
__device__ float g_w2T [C_HID * C_G * C_INTER];

__device__ __forceinline__ uint32_t f2tf32(float f) {
    uint32_t r;
    asm("cvt.rna.tf32.f32 %0, %1;" : "=r"(r) : "f"(f));
    return r;
}
__device__ __forceinline__ float tf32r(float f) { return __uint_as_float(f2tf32(f)); }

__device__ __forceinline__ void mma_tf32(float& c0, float& c1, float& c2, float& c3,
                                         uint32_t a0, uint32_t a1, uint32_t a2, uint32_t a3,
                                         uint32_t b0, uint32_t b1) {
    asm volatile(
        "mma.sync.aligned.m16n8k8.row.col.f32.tf32.tf32.f32 "
        "{%0,%1,%2,%3}, {%4,%5,%6,%7}, {%8,%9}, {%0,%1,%2,%3};"
        : "+f"(c0), "+f"(c1), "+f"(c2), "+f"(c3)
        : "r"(a0), "r"(a1), "r"(a2), "r"(a3), "r"(b0), "r"(b1));
}

__device__ __forceinline__ void ldsm4(uint32_t& r0, uint32_t& r1, uint32_t& r2, uint32_t& r3,
                                      uint32_t addr) {
    asm volatile("ldmatrix.sync.aligned.m8n8.x4.shared.b16 {%0,%1,%2,%3}, [%4];"
                 : "=r"(r0), "=r"(r1), "=r"(r2), "=r"(r3) : "r"(addr));
}

__device__ __forceinline__ void cp_async16(uint32_t saddr, const void* g) {
    asm volatile("cp.async.cg.shared.global [%0], [%1], 16;\n" :: "r"(saddr), "l"(g));
}
__device__ __forceinline__ void cp_commit() { asm volatile("cp.async.commit_group;\n"); }
template<int N>
__device__ __forceinline__ void cp_wait() { asm volatile("cp.async.wait_group %0;\n" :: "n"(N)); }

// ---------------------------------------------------------------------------
// cp.async pipelined tf32 GEMM.
// A [M][K] row-major (activations, k-contiguous, pre-rounded tf32 values),
// B [N][K] (pre-transposed+rounded weights, k-contiguous).
// SPLIT=1: hi/lo 3-term; S=2 stages, 4 planes. SPLIT=0: S=3 stages, 2 planes.
// EPI: 0 = plain fp32 C; 1 = tf32-rounded C; 2 = write hi->C, lo->C2.
// Tiles: 128x128xBK32, 256 threads (2x4 warps).
// ---------------------------------------------------------------------------
template<int SPLIT, int EPI>
__global__ void __launch_bounds__(256)
gemm_cp(const float* __restrict__ A,  const float* __restrict__ Alo,
        const float* __restrict__ Bt, const float* __restrict__ Btlo,
        float* __restrict__ C, float* __restrict__ C2,
        int K, int lda, int ldb, int ldc,
        long long azA, long long azB, long long azC) {
    constexpr int BK     = 32;
    constexpr int LDSR   = 36;                 // floats per smem row (144B, 16B aligned)
    constexpr int PLANE  = 128 * LDSR;         // floats
    constexpr int PLANEB = PLANE * 4;          // bytes
    constexpr int NPL    = SPLIT ? 4 : 2;
    constexpr int S      = SPLIT ? 2 : 3;
    constexpr int STAGEB = NPL * PLANEB;

    extern __shared__ float sm[];
    const uint32_t sbase = (uint32_t)__cvta_generic_to_shared(sm);

    const int tid  = threadIdx.x;
    const int warp = tid >> 5;
    const int lane = tid & 31;
    const int wm   = (warp >> 2) * 64;
    const int wn   = (warp & 3) * 32;
    const int grp  = lane >> 2;
    const int tig  = lane & 3;

    const int arow   = lane & 15;
    const int aoff16 = (lane >> 4) * 16;
    const int bsel   = (lane >> 4) & 1;
    const int boff16 = ((lane >> 3) & 1) * 16;
    const int brow   = lane & 7;

    const float* Ab  = A  + (size_t)blockIdx.z * azA + (size_t)blockIdx.y * 128 * lda;
    const float* Bb  = Bt + (size_t)blockIdx.z * azB + (size_t)blockIdx.x * 128 * ldb;
    const float* A2b = SPLIT ? Alo  + (size_t)blockIdx.z * azA + (size_t)blockIdx.y * 128 * lda : nullptr;
    const float* B2b = SPLIT ? Btlo + (size_t)blockIdx.z * azB + (size_t)blockIdx.x * 128 * ldb : nullptr;

    float acc[4][4][4];
#pragma unroll
    for (int i = 0; i < 4; i++)
#pragma unroll
        for (int j = 0; j < 4; j++)
#pragma unroll
            for (int r = 0; r < 4; r++) acc[i][j][r] = 0.f;

    auto issue = [&](int kt) {
        const int k0 = kt * BK;
        const uint32_t sa = sbase + (uint32_t)((kt % S) * STAGEB);
#pragma unroll
        for (int i = 0; i < 4; i++) {
            int c = tid + i * 256;
            int m = c >> 3, kc = (c & 7) * 4;
            cp_async16(sa + (uint32_t)(m * LDSR + kc) * 4, Ab + (size_t)m * lda + k0 + kc);
        }
#pragma unroll
        for (int i = 0; i < 4; i++) {
            int c = tid + i * 256;
            int n = c >> 3, kc = (c & 7) * 4;
            cp_async16(sa + PLANEB + (uint32_t)(n * LDSR + kc) * 4, Bb + (size_t)n * ldb + k0 + kc);
        }
        if (SPLIT) {
#pragma unroll
            for (int i = 0; i < 4; i++) {
                int c = tid + i * 256;
                int m = c >> 3, kc = (c & 7) * 4;
                cp_async16(sa + 2 * PLANEB + (uint32_t)(m * LDSR + kc) * 4, A2b + (size_t)m * lda + k0 + kc);
            }
#pragma unroll
            for (int i = 0; i < 4; i++) {
                int c = tid + i * 256;
                int n = c >> 3, kc = (c & 7) * 4;
                cp_async16(sa + 3 * PLANEB + (uint32_t)(n * LDSR + kc) * 4, B2b + (size_t)n * ldb + k0 + kc);
            }
        }
        cp_commit();
    };

    auto compute = [&](int st) {
        const uint32_t stb   = sbase + (uint32_t)(st * STAGEB);
        const uint32_t a_hi0 = stb + (uint32_t)(wm + arow) * (LDSR * 4) + aoff16;
        const uint32_t b_hi0 = stb + PLANEB + (uint32_t)(wn + bsel * 8 + brow) * (LDSR * 4) + boff16;
#pragma unroll
        for (int ks = 0; ks < BK / 8; ks++) {
            const uint32_t kb = ks * 32;
            uint32_t ah[4][4], bh[2][4];
#pragma unroll
            for (int mi = 0; mi < 4; mi++)
                ldsm4(ah[mi][0], ah[mi][1], ah[mi][2], ah[mi][3],
                      a_hi0 + mi * (16 * LDSR * 4) + kb);
#pragma unroll
            for (int p = 0; p < 2; p++)
                ldsm4(bh[p][0], bh[p][1], bh[p][2], bh[p][3],
                      b_hi0 + p * (16 * LDSR * 4) + kb);

            uint32_t al[4][4], bl[2][4];
            if (SPLIT) {
#pragma unroll
                for (int mi = 0; mi < 4; mi++)
                    ldsm4(al[mi][0], al[mi][1], al[mi][2], al[mi][3],
                          a_hi0 + 2 * PLANEB + mi * (16 * LDSR * 4) + kb);
#pragma unroll
                for (int p = 0; p < 2; p++)
                    ldsm4(bl[p][0], bl[p][1], bl[p][2], bl[p][3],
                          b_hi0 + 2 * PLANEB + p * (16 * LDSR * 4) + kb);
            }
#pragma unroll
            for (int mi = 0; mi < 4; mi++)
#pragma unroll
                for (int ni = 0; ni < 4; ni++) {
                    const int p = ni >> 1, q = (ni & 1) * 2;
                    mma_tf32(acc[mi][ni][0], acc[mi][ni][1], acc[mi][ni][2], acc[mi][ni][3],
                             ah[mi][0], ah[mi][1], ah[mi][2], ah[mi][3],
                             bh[p][q], bh[p][q + 1]);
                    if (SPLIT) {
                        mma_tf32(acc[mi][ni][0], acc[mi][ni][1], acc[mi][ni][2], acc[mi][ni][3],
                                 al[mi][0], al[mi][1], al[mi][2], al[mi][3],
                                 bh[p][q], bh[p][q + 1]);
                        mma_tf32(acc[mi][ni][0], acc[mi][ni][1], acc[mi][ni][2], acc[mi][ni][3],
                                 ah[mi][0], ah[mi][1], ah[mi][2], ah[mi][3],
                                 bl[p][q], bl[p][q + 1]);
                    }
                }
        }
    };

    const int KT = K / BK;
    for (int i = 0; i < S; i++) {
        if (i < KT) issue(i); else cp_commit();
    }
    for (int kt = 0; kt < KT; kt++) {
        cp_wait<S - 1>();
        __syncthreads();
        compute(kt % S);
        __syncthreads();
        if (kt + S < KT) issue(kt + S); else cp_commit();
    }

    C  += (size_t)blockIdx.z * azC;
    if (EPI == 2) C2 += (size_t)blockIdx.z * azC;
#pragma unroll
    for (int mi = 0; mi < 4; mi++) {
        int m0 = blockIdx.y * 128 + wm + mi * 16 + grp;
#pragma unroll
        for (int ni = 0; ni < 4; ni++) {
            int n = blockIdx.x * 128 + wn + ni * 8 + tig * 2;
#pragma unroll
            for (int half = 0; half < 2; half++) {
                size_t off = (size_t)(m0 + half * 8) * ldc + n;
                float v0 = acc[mi][ni][half * 2], v1 = acc[mi][ni][half * 2 + 1];
                if (EPI == 0) {
                    *(float2*)(C + off) = make_float2(v0, v1);
                } else if (EPI == 1) {
                    *(float2*)(C + off) = make_float2(tf32r(v0), tf32r(v1));
                } else {
                    float h0 = tf32r(v0), h1 = tf32r(v1);
                    *(float2*)(C  + off) = make_float2(h0, h1);
                    *(float2*)(C2 + off) = make_float2(tf32r(v0 - h0), tf32r(v1 - h1));
                }
            }
        }
    }
}

// ---------------------------------------------------------------------------
// Elementwise hi/lo split of a matrix (for h).
// ---------------------------------------------------------------------------
__global__ void split_kernel(const float* __restrict__ in, float* __restrict__ hi,
                             float* __restrict__ lo, int n) {
    int i = blockIdx.x * blockDim.x + threadIdx.x;
    if (i >= n) return;
    float v = in[i];
    float h = tf32r(v);
    hi[i] = h;
    lo[i] = tf32r(v - h);
}

// ---------------------------------------------------------------------------
// Tiled transpose + round: in[K][N] -> outT[N][K]. SPLIT writes hi & lo.
// Grid (N/32, K/32, batch), block (32, 8).
// ---------------------------------------------------------------------------
template<int SPLIT>
__global__ void transpose_round(const float* __restrict__ in,
                                float* __restrict__ outHi, float* __restrict__ outLo,
                                int K, int N, long long inBatch, long long outBatch) {
    __shared__ float tile[32][33];
    const float* inb = in + (size_t)blockIdx.z * inBatch;
    float* oh = outHi + (size_t)blockIdx.z * outBatch;
    float* ol = SPLIT ? outLo + (size_t)blockIdx.z * outBatch : nullptr;
    int n0 = blockIdx.x * 32, k0 = blockIdx.y * 32;
#pragma unroll
    for (int i = threadIdx.y; i < 32; i += 8)
        tile[i][threadIdx.x] = inb[(size_t)(k0 + i) * N + n0 + threadIdx.x];
    __syncthreads();
#pragma unroll
    for (int i = threadIdx.y; i < 32; i += 8) {
        float v = tile[threadIdx.x][i];               // in[k0+tx][n0+i]
        size_t off = (size_t)(n0 + i) * K + k0 + threadIdx.x;
        float h = tf32r(v);
        oh[off] = h;
        if (SPLIT) ol[off] = tf32r(v - h);
    }
}

// ---------------------------------------------------------------------------
// Partial RoPE + RMSNorm over D=128, in-place. One warp per row.
// ---------------------------------------------------------------------------
__global__ void rope_norm_kernel(float* __restrict__ x, const float* __restrict__ w,
                                 int nrows, int heads, int stride) {
    int gid  = blockIdx.x * blockDim.x + threadIdx.x;
    int wid  = gid >> 5;
    int lane = threadIdx.x & 31;
    if (wid >= nrows) return;
    int pos = (wid / heads) % C_T;

    float* row = x + (size_t)wid * stride;
    float a  = row[lane];
    float b2 = row[lane + 32];
    float c  = row[lane + 64];
    float e  = row[lane + 96];

    double invd = exp(-log(10000.0) * (double)(2 * lane) / 64.0);
    double ang  = (double)pos * invd;
    float cs = (float)cos(ang);
    float sn = (float)sin(ang);

    float r1 = a * cs - b2 * sn;
    float r2 = a * sn + b2 * cs;

    float ss = r1 * r1 + r2 * r2 + c * c + e * e;
#pragma unroll
    for (int off = 16; off; off >>= 1) ss += __shfl_xor_sync(0xffffffffu, ss, off);
    float rms = rsqrtf(ss * (1.0f / 128.0f) + 1e-6f);

    row[lane]      = r1 * rms * w[lane];
    row[lane + 32] = r2 * rms * w[lane + 32];
    row[lane + 64] = c  * rms * w[lane + 64];
    row[lane + 96] = e  * rms * w[lane + 96];
}

// ---------------------------------------------------------------------------
// Attention: block per (t, b); 16 warps = 16 heads. Output rounded to tf32.
// ---------------------------------------------------------------------------
__global__ void __launch_bounds__(512)
attn_kernel(const float* __restrict__ q, const float* __restrict__ kv,
            const float* __restrict__ sink, float* __restrict__ att) {
    int t = blockIdx.x, b = blockIdx.y;
    int h    = threadIdx.x >> 5;
    int lane = threadIdx.x & 31;
    int token = b * C_T + t;

    const float* qrow = q + (size_t)token * (C_H * C_D) + h * C_D;
    float q0 = qrow[lane], q1 = qrow[lane + 32], q2 = qrow[lane + 64], q3 = qrow[lane + 96];

    const float scale = 0.08838834764831845f;
    float m = -1e30f, ssum = 0.f;
    float a0 = 0.f, a1 = 0.f, a2 = 0.f, a3 = 0.f;

    int s0 = t - (C_WIN - 1);
    if (s0 < 0) s0 = 0;

    for (int s = s0; s <= t; ++s) {
        const float* krow = kv + (size_t)(b * C_T + s) * (2 * C_D);
        float d = q0 * krow[lane] + q1 * krow[lane + 32]
                + q2 * krow[lane + 64] + q3 * krow[lane + 96];
#pragma unroll
        for (int off = 16; off; off >>= 1) d += __shfl_xor_sync(0xffffffffu, d, off);
        d *= scale;

        float mn   = fmaxf(m, d);
        float corr = __expf(m - mn);
        float p    = __expf(d - mn);

        const float* vrow = krow + C_D;
        ssum = ssum * corr + p;
        a0 = a0 * corr + p * vrow[lane];
        a1 = a1 * corr + p * vrow[lane + 32];
        a2 = a2 * corr + p * vrow[lane + 64];
        a3 = a3 * corr + p * vrow[lane + 96];
        m = mn;
    }

    float sl   = sink[h];
    float mn   = fmaxf(m, sl);
    float corr = __expf(m - mn);
    ssum = ssum * corr + __expf(sl - mn);
    float inv = corr / ssum;

    float* orow = att + (size_t)token * (C_H * C_D) + h * C_D;
    orow[lane]      = tf32r(a0 * inv);
    orow[lane + 32] = tf32r(a1 * inv);
    orow[lane + 64] = tf32r(a2 * inv);
    orow[lane + 96] = tf32r(a3 * inv);
}

// ---------------------------------------------------------------------------
extern "C" void kernel_launch(void* const* d_in, const int* in_sizes, int n_in,
                              void* d_out, int out_size) {
    const float* h_in     = (const float*)d_in[0];
    const float* wq_comp  = (const float*)d_in[1];
    const float* wq_up    = (const float*)d_in[2];
    const float* wk       = (const float*)d_in[3];
    const float* wv       = (const float*)d_in[4];
    const float* q_norm_w = (const float*)d_in[5];
    const float* k_norm_w = (const float*)d_in[6];
    const float* sink     = (const float*)d_in[7];
    const float* out_w1   = (const float*)d_in[8];
    const float* out_w2   = (const float*)d_in[9];
    float* out = (float*)d_out;

    float *h_hi, *h_lo, *hc_hi, *hc_lo, *q, *kv, *att, *y1;
    float *wqcT_hi, *wqcT_lo, *wquT_hi, *wquT_lo, *wkvT_hi, *wkvT_lo, *w1T, *w2T;
    cudaGetSymbolAddress((void**)&h_hi,  g_h_hi);
    cudaGetSymbolAddress((void**)&h_lo,  g_h_lo);
    cudaGetSymbolAddress((void**)&hc_hi, g_hc_hi);
    cudaGetSymbolAddress((void**)&hc_lo, g_hc_lo);
    cudaGetSymbolAddress((void**)&q,     g_q);
    cudaGetSymbolAddress((void**)&kv,    g_kv);
    cudaGetSymbolAddress((void**)&att,   g_att);
    cudaGetSymbolAddress((void**)&y1,    g_y1);
    cudaGetSymbolAddress((void**)&wqcT_hi, g_wqcT_hi);
    cudaGetSymbolAddress((void**)&wqcT_lo, g_wqcT_lo);
    cudaGetSymbolAddress((void**)&wquT_hi, g_wquT_hi);
    cudaGetSymbolAddress((void**)&wquT_lo, g_wquT_lo);
    cudaGetSymbolAddress((void**)&wkvT_hi, g_wkvT_hi);
    cudaGetSymbolAddress((void**)&wkvT_lo, g_wkvT_lo);
    cudaGetSymbolAddress((void**)&w1T,   g_w1T);
    cudaGetSymbolAddress((void**)&w2T,   g_w2T);

    constexpr int SM_SPLIT  = 2 * 4 * 128 * 36 * 4;  // 147456 B
    constexpr int SM_SINGLE = 3 * 2 * 128 * 36 * 4;  // 110592 B
    cudaFuncSetAttribute(gemm_cp<1,2>, cudaFuncAttributeMaxDynamicSharedMemorySize, SM_SPLIT);
    cudaFuncSetAttribute(gemm_cp<1,0>, cudaFuncAttributeMaxDynamicSharedMemorySize, SM_SPLIT);
    cudaFuncSetAttribute(gemm_cp<0,1>, cudaFuncAttributeMaxDynamicSharedMemorySize, SM_SINGLE);
    cudaFuncSetAttribute(gemm_cp<0,0>, cudaFuncAttributeMaxDynamicSharedMemorySize, SM_SINGLE);

    dim3 tb(32, 8);

    // --- packing / pre-rounding ---
    split_kernel<<<(C_TOK * C_HID + 255) / 256, 256>>>(h_in, h_hi, h_lo, C_TOK * C_HID);
    transpose_round<1><<<dim3(C_QC/32, C_HID/32, 1), tb>>>(wq_comp, wqcT_hi, wqcT_lo, C_HID, C_QC, 0, 0);
    transpose_round<1><<<dim3(C_H*C_D/32, C_QC/32, 1), tb>>>(wq_up, wquT_hi, wquT_lo, C_QC, C_H*C_D, 0, 0);
    transpose_round<1><<<dim3(C_D/32, C_HID/32, 1), tb>>>(wk, wkvT_hi, wkvT_lo, C_HID, C_D, 0, 0);
    transpose_round<1><<<dim3(C_D/32, C_HID/32, 1), tb>>>(wv, wkvT_hi + (size_t)C_D*C_HID,
                                                          wkvT_lo + (size_t)C_D*C_HID, C_HID, C_D, 0, 0);
    transpose_round<0><<<dim3(C_INTER/32, (C_H/C_G)*C_D/32, C_G), tb>>>(
        out_w1, w1T, nullptr, (C_H/C_G)*C_D, C_INTER,
        (long long)(C_H/C_G)*C_D*C_INTER, (long long)C_INTER*(C_H/C_G)*C_D);
    transpose_round<0><<<dim3(C_HID/32, C_G*C_INTER/32, 1), tb>>>(
        out_w2, w2T, nullptr, C_G*C_INTER, C_HID, 0, 0);

    // --- 1) hc = h @ wq_comp (split, EPI=2 -> hc_hi/hc_lo) ---
    gemm_cp<1,2><<<dim3(C_QC/128, C_TOK/128, 1), 256, SM_SPLIT>>>(
        h_hi, h_lo, wqcT_hi, wqcT_lo, hc_hi, hc_lo,
        C_HID, C_HID, C_HID, C_QC, 0, 0, 0);

    // --- 2) q = hc @ wq_up (split, plain out) ---
    gemm_cp<1,0><<<dim3(C_H*C_D/128, C_TOK/128, 1), 256, SM_SPLIT>>>(
        hc_hi, hc_lo, wquT_hi, wquT_lo, q, nullptr,
        C_QC, C_QC, C_QC, C_H*C_D, 0, 0, 0);

    // --- 3) kv = h @ wkv (split, plain out) ---
    gemm_cp<1,0><<<dim3(2*C_D/128, C_TOK/128, 1), 256, SM_SPLIT>>>(
        h_hi, h_lo, wkvT_hi, wkvT_lo, kv, nullptr,
        C_HID, C_HID, C_HID, 2*C_D, 0, 0, 0);

    // --- 4) RoPE + RMSNorm ---
    {
        int rows = C_TOK * C_H;
        rope_norm_kernel<<<(rows * 32 + 255) / 256, 256>>>(q, q_norm_w, rows, C_H, C_D);
    }
    {
        int rows = C_TOK;
        rope_norm_kernel<<<(rows * 32 + 255) / 256, 256>>>(kv, k_norm_w, rows, 1, 2*C_D);
    }

    // --- 5) attention (tf32-rounded output) ---
    attn_kernel<<<dim3(C_T, C_B), 512>>>(q, kv, sink, att);

    // --- 6) y1 = grouped att @ w1 (single, z-batched, rounded out) ---
    gemm_cp<0,1><<<dim3(C_INTER/128, C_TOK/128, C_G), 256, SM_SINGLE>>>(
        att, nullptr, w1T, nullptr, y1, nullptr,
        (C_H/C_G)*C_D, C_H*C_D, (C_H/C_G)*C_D, C_G*C_INTER,
        (long long)(C_H/C_G)*C_D,                       // azA: column offset 512
        (long long)C_INTER*(C_H/C_G)*C_D,               // azB: per-group weight
        (long long)C_INTER);                            // azC: column offset 2048

    // --- 7) out = y1 @ out_w2 (single, plain out) ---
    gemm_cp<0,0><<<dim3(C_HID/128, C_TOK/128, 1), 256, SM_SINGLE>>>(
        y1, nullptr, w2T, nullptr, out, nullptr,
        C_G*C_INTER, C_G*C_INTER, C_G*C_INTER, C_HID, 0, 0, 0);
}

// round 6
// speedup vs baseline: 2.5960x; 1.0657x over previous
#include <cuda_runtime.h>
#include <math.h>
#include <stdint.h>

// Problem constants
constexpr int C_B    = 2;
constexpr int C_T    = 2048;
constexpr int C_HID  = 2048;
constexpr int C_H    = 16;
constexpr int C_D    = 128;
constexpr int C_WIN  = 512;
constexpr int C_QC   = 512;
constexpr int C_G    = 4;
constexpr int C_INTER= 2048;
constexpr int C_TOK  = C_B * C_T;

// ---------------------------------------------------------------------------
// Scratch (device globals)
// ---------------------------------------------------------------------------
__device__ float g_h_hi [C_TOK * C_HID];
__device__ float g_h_lo [C_TOK * C_HID];
__device__ float g_hc_hi[C_TOK * C_QC];
__device__ float g_hc_lo[C_TOK * C_QC];
__device__ float g_q    [C_TOK * C_H * C_D];
__device__ float g_kv   [C_TOK * 2 * C_D];
__device__ float g_att  [C_TOK * C_H * C_D];
__device__ float g_y1   [C_TOK * C_G * C_INTER];
// Transposed (+rounded) weights: [N][K]
__device__ float g_wqcT_hi[C_QC * C_HID];
__device__ float g_wqcT_lo[C_QC * C_HID];
__device__ float g_wquT_hi[C_H * C_D * C_QC];
__device__ float g_wquT_lo[C_H * C_D * C_QC];
__device__ float g_wkvT_hi[2 * C_D * C_HID];
__device__ float g_wkvT_lo[2 * C_D * C_HID];
__device__ float g_w1T [C_G * C_INTER * (C_H / C_G) * C_D];
__device__ float g_w2T [C_HID * C_G * C_INTER];

__device__ __forceinline__ uint32_t f2tf32(float f) {
    uint32_t r;
    asm("cvt.rna.tf32.f32 %0, %1;" : "=r"(r) : "f"(f));
    return r;
}
__device__ __forceinline__ float tf32r(float f) { return __uint_as_float(f2tf32(f)); }

__device__ __forceinline__ void mma_tf32(float& c0, float& c1, float& c2, float& c3,
                                         uint32_t a0, uint32_t a1, uint32_t a2, uint32_t a3,
                                         uint32_t b0, uint32_t b1) {
    asm volatile(
        "mma.sync.aligned.m16n8k8.row.col.f32.tf32.tf32.f32 "
        "{%0,%1,%2,%3}, {%4,%5,%6,%7}, {%8,%9}, {%0,%1,%2,%3};"
        : "+f"(c0), "+f"(c1), "+f"(c2), "+f"(c3)
        : "r"(a0), "r"(a1), "r"(a2), "r"(a3), "r"(b0), "r"(b1));
}

__device__ __forceinline__ void ldsm4(uint32_t& r0, uint32_t& r1, uint32_t& r2, uint32_t& r3,
                                      uint32_t addr) {
    asm volatile("ldmatrix.sync.aligned.m8n8.x4.shared.b16 {%0,%1,%2,%3}, [%4];"
                 : "=r"(r0), "=r"(r1), "=r"(r2), "=r"(r3) : "r"(addr));
}

__device__ __forceinline__ void cp_async16(uint32_t saddr, const void* g) {
    asm volatile("cp.async.cg.shared.global [%0], [%1], 16;\n" :: "r"(saddr), "l"(g));
}
__device__ __forceinline__ void cp_commit() { asm volatile("cp.async.commit_group;\n"); }
template<int N>
__device__ __forceinline__ void cp_wait() { asm volatile("cp.async.wait_group %0;\n" :: "n"(N)); }

// ---------------------------------------------------------------------------
// cp.async pipelined tf32 GEMM, 512 threads, 16 warps (4x4), warp tile 32x32.
// A [M][K] row-major, B [N][K] (k-contiguous), all values pre-rounded tf32.
// SPLIT=1: hi/lo 3-term (S=2). SPLIT=0: single (S=3).
// EPI: 0 plain; 1 tf32-rounded; 2 hi->C, lo->C2.
// ---------------------------------------------------------------------------
template<int SPLIT, int EPI>
__global__ void __launch_bounds__(512)
gemm_cp(const float* __restrict__ A,  const float* __restrict__ Alo,
        const float* __restrict__ Bt, const float* __restrict__ Btlo,
        float* __restrict__ C, float* __restrict__ C2,
        int K, int lda, int ldb, int ldc,
        long long azA, long long azB, long long azC) {
    constexpr int BK     = 32;
    constexpr int LDSR   = 36;                 // floats per smem row
    constexpr int PLANE  = 128 * LDSR;
    constexpr int PLANEB = PLANE * 4;
    constexpr int NPL    = SPLIT ? 4 : 2;
    constexpr int S      = SPLIT ? 2 : 3;
    constexpr int STAGEB = NPL * PLANEB;

    extern __shared__ float sm[];
    const uint32_t sbase = (uint32_t)__cvta_generic_to_shared(sm);

    const int tid  = threadIdx.x;
    const int warp = tid >> 5;
    const int lane = tid & 31;
    const int wm   = (warp >> 2) * 32;   // 4 m-warps
    const int wn   = (warp & 3) * 32;    // 4 n-warps
    const int grp  = lane >> 2;
    const int tig  = lane & 3;

    const int arow   = lane & 15;
    const int aoff16 = (lane >> 4) * 16;
    const int bsel   = (lane >> 4) & 1;
    const int boff16 = ((lane >> 3) & 1) * 16;
    const int brow   = lane & 7;

    const float* Ab  = A  + (size_t)blockIdx.z * azA + (size_t)blockIdx.y * 128 * lda;
    const float* Bb  = Bt + (size_t)blockIdx.z * azB + (size_t)blockIdx.x * 128 * ldb;
    const float* A2b = SPLIT ? Alo  + (size_t)blockIdx.z * azA + (size_t)blockIdx.y * 128 * lda : nullptr;
    const float* B2b = SPLIT ? Btlo + (size_t)blockIdx.z * azB + (size_t)blockIdx.x * 128 * ldb : nullptr;

    float acc[2][4][4];
#pragma unroll
    for (int i = 0; i < 2; i++)
#pragma unroll
        for (int j = 0; j < 4; j++)
#pragma unroll
            for (int r = 0; r < 4; r++) acc[i][j][r] = 0.f;

    auto issue = [&](int kt) {
        const int k0 = kt * BK;
        const uint32_t sa = sbase + (uint32_t)((kt % S) * STAGEB);
#pragma unroll
        for (int i = 0; i < 2; i++) {
            int c = tid + i * 512;
            int m = c >> 3, kc = (c & 7) * 4;
            cp_async16(sa + (uint32_t)(m * LDSR + kc) * 4, Ab + (size_t)m * lda + k0 + kc);
        }
#pragma unroll
        for (int i = 0; i < 2; i++) {
            int c = tid + i * 512;
            int n = c >> 3, kc = (c & 7) * 4;
            cp_async16(sa + PLANEB + (uint32_t)(n * LDSR + kc) * 4, Bb + (size_t)n * ldb + k0 + kc);
        }
        if (SPLIT) {
#pragma unroll
            for (int i = 0; i < 2; i++) {
                int c = tid + i * 512;
                int m = c >> 3, kc = (c & 7) * 4;
                cp_async16(sa + 2 * PLANEB + (uint32_t)(m * LDSR + kc) * 4, A2b + (size_t)m * lda + k0 + kc);
            }
#pragma unroll
            for (int i = 0; i < 2; i++) {
                int c = tid + i * 512;
                int n = c >> 3, kc = (c & 7) * 4;
                cp_async16(sa + 3 * PLANEB + (uint32_t)(n * LDSR + kc) * 4, B2b + (size_t)n * ldb + k0 + kc);
            }
        }
        cp_commit();
    };

    auto compute = [&](int st) {
        const uint32_t stb   = sbase + (uint32_t)(st * STAGEB);
        const uint32_t a_hi0 = stb + (uint32_t)(wm + arow) * (LDSR * 4) + aoff16;
        const uint32_t b_hi0 = stb + PLANEB + (uint32_t)(wn + bsel * 8 + brow) * (LDSR * 4) + boff16;
#pragma unroll
        for (int ks = 0; ks < BK / 8; ks++) {
            const uint32_t kb = ks * 32;
            uint32_t ah[2][4], bh[2][4];
#pragma unroll
            for (int mi = 0; mi < 2; mi++)
                ldsm4(ah[mi][0], ah[mi][1], ah[mi][2], ah[mi][3],
                      a_hi0 + mi * (16 * LDSR * 4) + kb);
#pragma unroll
            for (int p = 0; p < 2; p++)
                ldsm4(bh[p][0], bh[p][1], bh[p][2], bh[p][3],
                      b_hi0 + p * (16 * LDSR * 4) + kb);

            uint32_t al[2][4], bl[2][4];
            if (SPLIT) {
#pragma unroll
                for (int mi = 0; mi < 2; mi++)
                    ldsm4(al[mi][0], al[mi][1], al[mi][2], al[mi][3],
                          a_hi0 + 2 * PLANEB + mi * (16 * LDSR * 4) + kb);
#pragma unroll
                for (int p = 0; p < 2; p++)
                    ldsm4(bl[p][0], bl[p][1], bl[p][2], bl[p][3],
                          b_hi0 + 2 * PLANEB + p * (16 * LDSR * 4) + kb);
            }
#pragma unroll
            for (int mi = 0; mi < 2; mi++)
#pragma unroll
                for (int ni = 0; ni < 4; ni++) {
                    const int p = ni >> 1, q = (ni & 1) * 2;
                    mma_tf32(acc[mi][ni][0], acc[mi][ni][1], acc[mi][ni][2], acc[mi][ni][3],
                             ah[mi][0], ah[mi][1], ah[mi][2], ah[mi][3],
                             bh[p][q], bh[p][q + 1]);
                    if (SPLIT) {
                        mma_tf32(acc[mi][ni][0], acc[mi][ni][1], acc[mi][ni][2], acc[mi][ni][3],
                                 al[mi][0], al[mi][1], al[mi][2], al[mi][3],
                                 bh[p][q], bh[p][q + 1]);
                        mma_tf32(acc[mi][ni][0], acc[mi][ni][1], acc[mi][ni][2], acc[mi][ni][3],
                                 ah[mi][0], ah[mi][1], ah[mi][2], ah[mi][3],
                                 bl[p][q], bl[p][q + 1]);
                    }
                }
        }
    };

    const int KT = K / BK;
    for (int i = 0; i < S; i++) {
        if (i < KT) issue(i); else cp_commit();
    }
    for (int kt = 0; kt < KT; kt++) {
        cp_wait<S - 1>();
        __syncthreads();
        compute(kt % S);
        __syncthreads();
        if (kt + S < KT) issue(kt + S); else cp_commit();
    }

    C += (size_t)blockIdx.z * azC;
    if (EPI == 2) C2 += (size_t)blockIdx.z * azC;
#pragma unroll
    for (int mi = 0; mi < 2; mi++) {
        int m0 = blockIdx.y * 128 + wm + mi * 16 + grp;
#pragma unroll
        for (int ni = 0; ni < 4; ni++) {
            int n = blockIdx.x * 128 + wn + ni * 8 + tig * 2;
#pragma unroll
            for (int half = 0; half < 2; half++) {
                size_t off = (size_t)(m0 + half * 8) * ldc + n;
                float v0 = acc[mi][ni][half * 2], v1 = acc[mi][ni][half * 2 + 1];
                if (EPI == 0) {
                    *(float2*)(C + off) = make_float2(v0, v1);
                } else if (EPI == 1) {
                    *(float2*)(C + off) = make_float2(tf32r(v0), tf32r(v1));
                } else {
                    float h0 = tf32r(v0), h1 = tf32r(v1);
                    *(float2*)(C  + off) = make_float2(h0, h1);
                    *(float2*)(C2 + off) = make_float2(tf32r(v0 - h0), tf32r(v1 - h1));
                }
            }
        }
    }
}

// ---------------------------------------------------------------------------
__global__ void split_kernel(const float* __restrict__ in, float* __restrict__ hi,
                             float* __restrict__ lo, int n) {
    int i = blockIdx.x * blockDim.x + threadIdx.x;
    if (i >= n) return;
    float v = in[i];
    float h = tf32r(v);
    hi[i] = h;
    lo[i] = tf32r(v - h);
}

// ---------------------------------------------------------------------------
template<int SPLIT>
__global__ void transpose_round(const float* __restrict__ in,
                                float* __restrict__ outHi, float* __restrict__ outLo,
                                int K, int N, long long inBatch, long long outBatch) {
    __shared__ float tile[32][33];
    const float* inb = in + (size_t)blockIdx.z * inBatch;
    float* oh = outHi + (size_t)blockIdx.z * outBatch;
    float* ol = SPLIT ? outLo + (size_t)blockIdx.z * outBatch : nullptr;
    int n0 = blockIdx.x * 32, k0 = blockIdx.y * 32;
#pragma unroll
    for (int i = threadIdx.y; i < 32; i += 8)
        tile[i][threadIdx.x] = inb[(size_t)(k0 + i) * N + n0 + threadIdx.x];
    __syncthreads();
#pragma unroll
    for (int i = threadIdx.y; i < 32; i += 8) {
        float v = tile[threadIdx.x][i];
        size_t off = (size_t)(n0 + i) * K + k0 + threadIdx.x;
        float h = tf32r(v);
        oh[off] = h;
        if (SPLIT) ol[off] = tf32r(v - h);
    }
}

// ---------------------------------------------------------------------------
__global__ void rope_norm_kernel(float* __restrict__ x, const float* __restrict__ w,
                                 int nrows, int heads, int stride) {
    int gid  = blockIdx.x * blockDim.x + threadIdx.x;
    int wid  = gid >> 5;
    int lane = threadIdx.x & 31;
    if (wid >= nrows) return;
    int pos = (wid / heads) % C_T;

    float* row = x + (size_t)wid * stride;
    float a  = row[lane];
    float b2 = row[lane + 32];
    float c  = row[lane + 64];
    float e  = row[lane + 96];

    double invd = exp(-log(10000.0) * (double)(2 * lane) / 64.0);
    double ang  = (double)pos * invd;
    float cs = (float)cos(ang);
    float sn = (float)sin(ang);

    float r1 = a * cs - b2 * sn;
    float r2 = a * sn + b2 * cs;

    float ss = r1 * r1 + r2 * r2 + c * c + e * e;
#pragma unroll
    for (int off = 16; off; off >>= 1) ss += __shfl_xor_sync(0xffffffffu, ss, off);
    float rms = rsqrtf(ss * (1.0f / 128.0f) + 1e-6f);

    row[lane]      = r1 * rms * w[lane];
    row[lane + 32] = r2 * rms * w[lane + 32];
    row[lane + 64] = c  * rms * w[lane + 64];
    row[lane + 96] = e  * rms * w[lane + 96];
}

// ---------------------------------------------------------------------------
// Attention: block per (t, b); 16 warps = 16 heads. K/V staged through smem
// in chunks of 32 keys shared by all heads. float4 lanes (lane owns d=4*lane).
// ---------------------------------------------------------------------------
__global__ void __launch_bounds__(512)
attn_kernel(const float* __restrict__ q, const float* __restrict__ kv,
            const float* __restrict__ sink, float* __restrict__ att) {
    __shared__ float skv[32 * 2 * C_D];   // 32 keys x 256 floats = 32 KB

    int t = blockIdx.x, b = blockIdx.y;
    int h    = threadIdx.x >> 5;
    int lane = threadIdx.x & 31;
    int tid  = threadIdx.x;
    int token = b * C_T + t;

    const float4* q4p = (const float4*)(q + (size_t)token * (C_H * C_D) + h * C_D);
    float4 qv = q4p[lane];

    const float scale = 0.08838834764831845f;
    float m = -1e30f, ssum = 0.f;
    float4 av = make_float4(0.f, 0.f, 0.f, 0.f);

    int s0 = t - (C_WIN - 1);
    if (s0 < 0) s0 = 0;

    for (int c0 = s0; c0 <= t; c0 += 32) {
        int cnt = t - c0 + 1;
        if (cnt > 32) cnt = 32;
        __syncthreads();
        // load cnt keys (cnt * 64 float4s) cooperatively
        const float4* src = (const float4*)(kv + (size_t)(b * C_T + c0) * (2 * C_D));
        for (int i = tid; i < cnt * 64; i += 512)
            ((float4*)skv)[i] = src[i];
        __syncthreads();

        for (int j = 0; j < cnt; j++) {
            const float4* krow = (const float4*)(skv + j * (2 * C_D));
            float4 kvec = krow[lane];
            float d = qv.x * kvec.x + qv.y * kvec.y + qv.z * kvec.z + qv.w * kvec.w;
#pragma unroll
            for (int off = 16; off; off >>= 1) d += __shfl_xor_sync(0xffffffffu, d, off);
            d *= scale;

            float mn   = fmaxf(m, d);
            float corr = __expf(m - mn);
            float p    = __expf(d - mn);

            float4 vvec = krow[32 + lane];
            ssum = ssum * corr + p;
            av.x = av.x * corr + p * vvec.x;
            av.y = av.y * corr + p * vvec.y;
            av.z = av.z * corr + p * vvec.z;
            av.w = av.w * corr + p * vvec.w;
            m = mn;
        }
    }

    float sl   = sink[h];
    float mn   = fmaxf(m, sl);
    float corr = __expf(m - mn);
    ssum = ssum * corr + __expf(sl - mn);
    float inv = corr / ssum;

    float4* orow = (float4*)(att + (size_t)token * (C_H * C_D) + h * C_D);
    orow[lane] = make_float4(tf32r(av.x * inv), tf32r(av.y * inv),
                             tf32r(av.z * inv), tf32r(av.w * inv));
}

// ---------------------------------------------------------------------------
extern "C" void kernel_launch(void* const* d_in, const int* in_sizes, int n_in,
                              void* d_out, int out_size) {
    const float* h_in     = (const float*)d_in[0];
    const float* wq_comp  = (const float*)d_in[1];
    const float* wq_up    = (const float*)d_in[2];
    const float* wk       = (const float*)d_in[3];
    const float* wv       = (const float*)d_in[4];
    const float* q_norm_w = (const float*)d_in[5];
    const float* k_norm_w = (const float*)d_in[6];
    const float* sink     = (const float*)d_in[7];
    const float* out_w1   = (const float*)d_in[8];
    const float* out_w2   = (const float*)d_in[9];
    float* out = (float*)d_out;

    float *h_hi, *h_lo, *hc_hi, *hc_lo, *q, *kv, *att, *y1;
    float *wqcT_hi, *wqcT_lo, *wquT_hi, *wquT_lo, *wkvT_hi, *wkvT_lo, *w1T, *w2T;
    cudaGetSymbolAddress((void**)&h_hi,  g_h_hi);
    cudaGetSymbolAddress((void**)&h_lo,  g_h_lo);
    cudaGetSymbolAddress((void**)&hc_hi, g_hc_hi);
    cudaGetSymbolAddress((void**)&hc_lo, g_hc_lo);
    cudaGetSymbolAddress((void**)&q,     g_q);
    cudaGetSymbolAddress((void**)&kv,    g_kv);
    cudaGetSymbolAddress((void**)&att,   g_att);
    cudaGetSymbolAddress((void**)&y1,    g_y1);
    cudaGetSymbolAddress((void**)&wqcT_hi, g_wqcT_hi);
    cudaGetSymbolAddress((void**)&wqcT_lo, g_wqcT_lo);
    cudaGetSymbolAddress((void**)&wquT_hi, g_wquT_hi);
    cudaGetSymbolAddress((void**)&wquT_lo, g_wquT_lo);
    cudaGetSymbolAddress((void**)&wkvT_hi, g_wkvT_hi);
    cudaGetSymbolAddress((void**)&wkvT_lo, g_wkvT_lo);
    cudaGetSymbolAddress((void**)&w1T,   g_w1T);
    cudaGetSymbolAddress((void**)&w2T,   g_w2T);

    constexpr int SM_SPLIT  = 2 * 4 * 128 * 36 * 4;  // 147456 B
    constexpr int SM_SINGLE = 3 * 2 * 128 * 36 * 4;  // 110592 B
    cudaFuncSetAttribute(gemm_cp<1,2>, cudaFuncAttributeMaxDynamicSharedMemorySize, SM_SPLIT);
    cudaFuncSetAttribute(gemm_cp<1,0>, cudaFuncAttributeMaxDynamicSharedMemorySize, SM_SPLIT);
    cudaFuncSetAttribute(gemm_cp<0,1>, cudaFuncAttributeMaxDynamicSharedMemorySize, SM_SINGLE);
    cudaFuncSetAttribute(gemm_cp<0,0>, cudaFuncAttributeMaxDynamicSharedMemorySize, SM_SINGLE);

    dim3 tb(32, 8);

    // --- packing / pre-rounding ---
    split_kernel<<<(C_TOK * C_HID + 255) / 256, 256>>>(h_in, h_hi, h_lo, C_TOK * C_HID);
    transpose_round<1><<<dim3(C_QC/32, C_HID/32, 1), tb>>>(wq_comp, wqcT_hi, wqcT_lo, C_HID, C_QC, 0, 0);
    transpose_round<1><<<dim3(C_H*C_D/32, C_QC/32, 1), tb>>>(wq_up, wquT_hi, wquT_lo, C_QC, C_H*C_D, 0, 0);
    transpose_round<1><<<dim3(C_D/32, C_HID/32, 1), tb>>>(wk, wkvT_hi, wkvT_lo, C_HID, C_D, 0, 0);
    transpose_round<1><<<dim3(C_D/32, C_HID/32, 1), tb>>>(wv, wkvT_hi + (size_t)C_D*C_HID,
                                                          wkvT_lo + (size_t)C_D*C_HID, C_HID, C_D, 0, 0);
    transpose_round<0><<<dim3(C_INTER/32, (C_H/C_G)*C_D/32, C_G), tb>>>(
        out_w1, w1T, nullptr, (C_H/C_G)*C_D, C_INTER,
        (long long)(C_H/C_G)*C_D*C_INTER, (long long)C_INTER*(C_H/C_G)*C_D);
    transpose_round<0><<<dim3(C_HID/32, C_G*C_INTER/32, 1), tb>>>(
        out_w2, w2T, nullptr, C_G*C_INTER, C_HID, 0, 0);

    // --- 1) hc = h @ wq_comp (split, hi/lo out) ---
    gemm_cp<1,2><<<dim3(C_QC/128, C_TOK/128, 1), 512, SM_SPLIT>>>(
        h_hi, h_lo, wqcT_hi, wqcT_lo, hc_hi, hc_lo,
        C_HID, C_HID, C_HID, C_QC, 0, 0, 0);

    // --- 2) q = hc @ wq_up (split) ---
    gemm_cp<1,0><<<dim3(C_H*C_D/128, C_TOK/128, 1), 512, SM_SPLIT>>>(
        hc_hi, hc_lo, wquT_hi, wquT_lo, q, nullptr,
        C_QC, C_QC, C_QC, C_H*C_D, 0, 0, 0);

    // --- 3) kv = h @ wkv (split) ---
    gemm_cp<1,0><<<dim3(2*C_D/128, C_TOK/128, 1), 512, SM_SPLIT>>>(
        h_hi, h_lo, wkvT_hi, wkvT_lo, kv, nullptr,
        C_HID, C_HID, C_HID, 2*C_D, 0, 0, 0);

    // --- 4) RoPE + RMSNorm ---
    {
        int rows = C_TOK * C_H;
        rope_norm_kernel<<<(rows * 32 + 255) / 256, 256>>>(q, q_norm_w, rows, C_H, C_D);
    }
    {
        int rows = C_TOK;
        rope_norm_kernel<<<(rows * 32 + 255) / 256, 256>>>(kv, k_norm_w, rows, 1, 2*C_D);
    }

    // --- 5) attention (tf32-rounded output) ---
    attn_kernel<<<dim3(C_T, C_B), 512>>>(q, kv, sink, att);

    // --- 6) y1 = grouped att @ w1 (single, z-batched, rounded out) ---
    gemm_cp<0,1><<<dim3(C_INTER/128, C_TOK/128, C_G), 512, SM_SINGLE>>>(
        att, nullptr, w1T, nullptr, y1, nullptr,
        (C_H/C_G)*C_D, C_H*C_D, (C_H/C_G)*C_D, C_G*C_INTER,
        (long long)(C_H/C_G)*C_D,
        (long long)C_INTER*(C_H/C_G)*C_D,
        (long long)C_INTER);

    // --- 7) out = y1 @ out_w2 (single) ---
    gemm_cp<0,0><<<dim3(C_HID/128, C_TOK/128, 1), 512, SM_SINGLE>>>(
        y1, nullptr, w2T, nullptr, out, nullptr,
        C_G*C_INTER, C_G*C_INTER, C_G*C_INTER, C_HID, 0, 0, 0);
}